// round 12
// baseline (speedup 1.0000x reference)
#include <cuda_runtime.h>
#include <cuda_bf16.h>
#include <math_constants.h>

// Shapes
#define B_  16
#define L_  4096
#define D_  1024
#define LC  64            // L-rows per mega-kernel block
#define NLC (L_ / LC)     // 64 chunks per batch

// Scratch (allocation-free rule: __device__ globals)
__device__ float g_decfeat[B_ * D_];          // dec_hidden @ W^T + b
__device__ float g_e[B_ * L_];                // unnormalized exp(score)*mask
__device__ float g_Spart[B_ * NLC];           // per-chunk partial sums of e
__device__ float g_ctxpart[B_ * NLC * D_];    // per-chunk unnormalized context

__device__ __forceinline__ float tanh_approx(float x) {
    float y;
    asm("tanh.approx.f32 %0, %1;" : "=f"(y) : "f"(x));
    return y;
}

__device__ __forceinline__ float warp_sum(float v) {
    #pragma unroll
    for (int o = 16; o; o >>= 1) v += __shfl_xor_sync(0xFFFFFFFFu, v, o);
    return v;
}

// ---------------------------------------------------------------------------
// K1: dec_feature[b,i] = sum_j dec_hidden[b,j] * W[i,j] + bias[i]
// one warp per (b,i); W row contiguous -> coalesced float4 loads
// ---------------------------------------------------------------------------
__global__ void k_decfeat(const float* __restrict__ dh,
                          const float* __restrict__ W,
                          const float* __restrict__ bias,
                          float* __restrict__ out) {
    int warp = (blockIdx.x * blockDim.x + threadIdx.x) >> 5;
    int lane = threadIdx.x & 31;
    if (warp >= B_ * D_) return;
    int b = warp >> 10;          // / D_
    int i = warp & (D_ - 1);
    const float4* wrow = (const float4*)(W + (size_t)i * D_);
    const float4* x    = (const float4*)(dh + (size_t)b * D_);
    float acc = 0.f;
    #pragma unroll
    for (int k = 0; k < 8; k++) {
        float4 wv = wrow[lane + k * 32];
        float4 xv = x[lane + k * 32];
        acc += wv.x * xv.x + wv.y * xv.y + wv.z * xv.z + wv.w * xv.w;
    }
    acc = warp_sum(acc);
    if (lane == 0) out[warp] = acc + bias[i];
}

// ---------------------------------------------------------------------------
// M: fused score + unnormalized-context mega-kernel.
// Block (lc, b) owns rows [lc*64, lc*64+64).
// Phase A: 4 warps x 16 rows: v_l = exp(score_l) * mask_l  (shift-free softmax
//          numerator -- scores are bounded, no overflow), v -> smem + g_e,
//          chunk sum -> g_Spart (private slot, no atomics).
// Phase B: acc[d] = sum_l v_l * enc[l, d]; block walks its 256KB enc chunk
//          fully sequentially (full 4KB row per iteration); partial -> private
//          g_ctxpart slot (no atomics, no pre-zeroing).
// ---------------------------------------------------------------------------
__global__ void __launch_bounds__(128, 8) k_mega(
        const float* __restrict__ ef,
        const float* __restrict__ enc,
        const float* __restrict__ mask,
        const float* __restrict__ cov,
        const float* __restrict__ wcov,
        const float* __restrict__ wscore,
        const float* __restrict__ decf) {
    int b  = blockIdx.y;
    int lc = blockIdx.x;
    int t  = threadIdx.x;            // 0..127
    int wid  = t >> 5;               // 0..3
    int lane = t & 31;
    int l0 = lc * LC;

    __shared__ float e_s[LC];
    __shared__ float wsum[4];

    // ---- Phase A: 16 rows per warp ----
    const float4* df = (const float4*)(decf + (size_t)b * D_);
    const float4* wc = (const float4*)wcov;
    const float4* ws = (const float4*)wscore;
    float local = 0.f;
    for (int i = 0; i < 16; i++) {
        int r = wid * 16 + i;
        int l = l0 + r;
        const float4* e4 = (const float4*)(ef + ((size_t)b * L_ + l) * D_);
        float c = cov[(size_t)b * L_ + l];
        float acc = 0.f;
        #pragma unroll
        for (int k = 0; k < 8; k++) {
            int idx = lane + k * 32;
            float4 ev = __ldcs(e4 + idx);   // streaming: read-once tensor
            float4 dv = df[idx];
            float4 cv = wc[idx];
            float4 sv = ws[idx];
            acc += tanh_approx(fmaf(c, cv.x, ev.x + dv.x)) * sv.x;
            acc += tanh_approx(fmaf(c, cv.y, ev.y + dv.y)) * sv.y;
            acc += tanh_approx(fmaf(c, cv.z, ev.z + dv.z)) * sv.z;
            acc += tanh_approx(fmaf(c, cv.w, ev.w + dv.w)) * sv.w;
        }
        acc = warp_sum(acc);
        if (lane == 0) {
            float v = __expf(acc) * mask[(size_t)b * L_ + l];
            e_s[r] = v;
            g_e[(size_t)b * L_ + l] = v;
            local += v;
        }
    }
    if (lane == 0) wsum[wid] = local;
    __syncthreads();
    if (t == 0)
        g_Spart[b * NLC + lc] = wsum[0] + wsum[1] + wsum[2] + wsum[3];

    // ---- Phase B: weighted accumulation over the 64-row chunk ----
    const float* ebase = enc + ((size_t)b * L_ + l0) * D_;
    float acc[8] = {0.f, 0.f, 0.f, 0.f, 0.f, 0.f, 0.f, 0.f};
    #pragma unroll 2
    for (int l = 0; l < LC; l++) {
        float w = e_s[l];
        const float* row = ebase + (size_t)l * D_ + t;
        #pragma unroll
        for (int d = 0; d < 8; d++)
            acc[d] = fmaf(w, row[d * 128], acc[d]);
    }
    float* cp = g_ctxpart + ((size_t)(b * NLC + lc)) * D_ + t;
    #pragma unroll
    for (int d = 0; d < 8; d++)
        cp[d * 128] = acc[d];
}

// ---------------------------------------------------------------------------
// F: finalize. One block (1024 threads) per batch.
//   S_b = sum of 64 partials; inv = 1/S_b
//   attn = g_e * inv; new_coverage = attn + cov
//   context[d] = inv * sum_{lc} ctxpart[lc][d]
// ---------------------------------------------------------------------------
__global__ void k_final(const float* __restrict__ cov,
                        float* __restrict__ attn,
                        float* __restrict__ newcov,
                        float* __restrict__ context) {
    int b = blockIdx.x;
    int t = threadIdx.x;               // 0..1023
    __shared__ float arr[NLC];
    __shared__ float sinv;

    if (t < NLC) arr[t] = g_Spart[b * NLC + t];
    __syncthreads();
    if (t < 32) {
        float v = arr[t] + arr[t + 32];
        v = warp_sum(v);
        if (t == 0) sinv = 1.f / v;
    }
    __syncthreads();
    float inv = sinv;

    // context: reduce the 64 chunk partials
    const float* cp = g_ctxpart + (size_t)b * NLC * D_ + t;
    float ctx = 0.f;
    #pragma unroll 8
    for (int c = 0; c < NLC; c++)
        ctx += cp[(size_t)c * D_];
    context[(size_t)b * D_ + t] = ctx * inv;

    // attn + new_coverage
    #pragma unroll
    for (int j = 0; j < 4; j++) {
        int idx = t + j * 1024;
        float a = g_e[(size_t)b * L_ + idx] * inv;
        attn[(size_t)b * L_ + idx]   = a;
        newcov[(size_t)b * L_ + idx] = a + cov[(size_t)b * L_ + idx];
    }
}

// ---------------------------------------------------------------------------
extern "C" void kernel_launch(void* const* d_in, const int* in_sizes, int n_in,
                              void* d_out, int out_size) {
    const float* dec_hidden  = (const float*)d_in[0];  // [16,1024]
    const float* enc_output  = (const float*)d_in[1];  // [16,4096,1024]
    const float* enc_feature = (const float*)d_in[2];  // [16,4096,1024]
    const float* enc_mask    = (const float*)d_in[3];  // [16,4096]
    // d_in[4] = sec_attn -- dead code in the reference, unused
    const float* coverage    = (const float*)d_in[5];  // [16,4096]
    const float* W_feat      = (const float*)d_in[6];  // [1024,1024]
    const float* b_feat      = (const float*)d_in[7];  // [1024]
    const float* w_score     = (const float*)d_in[8];  // [1024]
    const float* w_cov       = (const float*)d_in[9];  // [1024]

    float* out = (float*)d_out;
    float* attn_out   = out;                     // [16,4096]
    float* context    = out + B_ * L_;           // [16,1024]
    float* newcov_out = out + B_ * L_ + B_ * D_; // [16,4096]

    float* decf; cudaGetSymbolAddress((void**)&decf, g_decfeat);

    // K1: dec_feature GEMV — 16384 warps, 256 thr/block
    k_decfeat<<<(B_ * D_ * 32) / 256, 256>>>(dec_hidden, W_feat, b_feat, decf);

    // M: fused scores + unnormalized context — 1024 blocks, all resident
    dim3 gm(NLC, B_);
    k_mega<<<gm, 128>>>(enc_feature, enc_output, enc_mask, coverage,
                        w_cov, w_score, decf);

    // F: normalize + emit all three outputs
    k_final<<<B_, 1024>>>(coverage, attn_out, newcov_out, context);
}

// round 16
// speedup vs baseline: 1.2832x; 1.2832x over previous
#include <cuda_runtime.h>
#include <cuda_bf16.h>
#include <math_constants.h>

// Shapes
#define B_  16
#define L_  4096
#define D_  1024

// Scratch (allocation-free rule: __device__ globals)
__device__ float g_decfeat[B_ * D_];   // dec_hidden @ W^T + b
__device__ float g_score[B_ * L_];     // pre-softmax scores

__device__ __forceinline__ float tanh_approx(float x) {
    float y;
    asm("tanh.approx.f32 %0, %1;" : "=f"(y) : "f"(x));
    return y;
}

__device__ __forceinline__ float warp_sum(float v) {
    #pragma unroll
    for (int o = 16; o; o >>= 1) v += __shfl_xor_sync(0xFFFFFFFFu, v, o);
    return v;
}
__device__ __forceinline__ float warp_max(float v) {
    #pragma unroll
    for (int o = 16; o; o >>= 1) v = fmaxf(v, __shfl_xor_sync(0xFFFFFFFFu, v, o));
    return v;
}

// ---------------------------------------------------------------------------
// K1: dec_feature[b,i] = sum_j dec_hidden[b,j] * W[i,j] + bias[i]
// Fixed: W row read ONCE per half-batch (was 16x -> 64MB L2 traffic).
// Block = 8 warps; block (gx, gy) stages dec_hidden[gy*8 .. gy*8+8) in smem
// (32KB), warp w streams W row i = gx*8 + w and produces 8 outputs at once.
// 8 independent FMA chains per lane -> ILP; W traffic total = 2 x 4MB.
// ---------------------------------------------------------------------------
__global__ void __launch_bounds__(256) k_decfeat(
        const float* __restrict__ dh,
        const float* __restrict__ W,
        const float* __restrict__ bias,
        float* __restrict__ out) {
    __shared__ float4 dh_s[8 * (D_ / 4)];       // 8 batches x 1024 floats = 32KB
    int t = threadIdx.x;                         // 0..255
    int wid = t >> 5, lane = t & 31;
    int b0 = blockIdx.y * 8;
    int i  = blockIdx.x * 8 + wid;               // W row / output feature

    // stage dec_hidden[b0 .. b0+8) -- 2048 float4 by 256 threads
    const float4* dh4 = (const float4*)(dh + (size_t)b0 * D_);
    #pragma unroll
    for (int j = 0; j < 8; j++)
        dh_s[t + j * 256] = dh4[t + j * 256];
    __syncthreads();

    const float4* wrow = (const float4*)(W + (size_t)i * D_);
    float acc[8] = {0.f, 0.f, 0.f, 0.f, 0.f, 0.f, 0.f, 0.f};
    #pragma unroll
    for (int k = 0; k < 8; k++) {
        int idx = lane + k * 32;                 // float4 index within row
        float4 wv = wrow[idx];
        #pragma unroll
        for (int b = 0; b < 8; b++) {
            float4 xv = dh_s[b * (D_ / 4) + idx];
            acc[b] += wv.x * xv.x + wv.y * xv.y + wv.z * xv.z + wv.w * xv.w;
        }
    }
    float bi = bias[i];
    #pragma unroll
    for (int b = 0; b < 8; b++) {
        float v = warp_sum(acc[b]);
        if (lane == 0) out[(size_t)(b0 + b) * D_ + i] = v + bi;
    }
}

// ---------------------------------------------------------------------------
// K2: score[b,l] = sum_d tanh(enc_feature[b,l,d] + dec_feature[b,d]
//                              + coverage[b,l]*w_cov[d]) * w_score[d]
// one warp per (b,l); streams enc_feature (256 MB) once -> __ldcs evict-first
// ---------------------------------------------------------------------------
__global__ void k_score(const float* __restrict__ ef,
                        const float* __restrict__ cov,
                        const float* __restrict__ wcov,
                        const float* __restrict__ wscore,
                        const float* __restrict__ decf,
                        float* __restrict__ score) {
    int warp = (blockIdx.x * blockDim.x + threadIdx.x) >> 5;
    int lane = threadIdx.x & 31;
    if (warp >= B_ * L_) return;
    int b = warp >> 12;          // / L_
    const float4* e  = (const float4*)(ef + (size_t)warp * D_);
    const float4* df = (const float4*)(decf + (size_t)b * D_);
    const float4* wc = (const float4*)wcov;
    const float4* ws = (const float4*)wscore;
    float c = cov[warp];
    float acc = 0.f;
    #pragma unroll
    for (int k = 0; k < 8; k++) {
        int idx = lane + k * 32;
        float4 ev = __ldcs(e + idx);   // streaming: read-once tensor
        float4 dv = df[idx];
        float4 cv = wc[idx];
        float4 sv = ws[idx];
        acc += tanh_approx(fmaf(c, cv.x, ev.x + dv.x)) * sv.x;
        acc += tanh_approx(fmaf(c, cv.y, ev.y + dv.y)) * sv.y;
        acc += tanh_approx(fmaf(c, cv.z, ev.z + dv.z)) * sv.z;
        acc += tanh_approx(fmaf(c, cv.w, ev.w + dv.w)) * sv.w;
    }
    acc = warp_sum(acc);
    if (lane == 0) score[warp] = acc;
}

// ---------------------------------------------------------------------------
// K3: per-batch masked softmax + renormalize (denominators cancel ->
//     attn_i = e^{s_i-max} * m_i / sum_j e^{s_j-max} * m_j),
//     new_coverage = attn + coverage, and zero the context region.
// one block (1024 threads) per batch
// ---------------------------------------------------------------------------
__global__ void k_softmax(const float* __restrict__ score,
                          const float* __restrict__ mask,
                          const float* __restrict__ cov,
                          float* __restrict__ attn,
                          float* __restrict__ newcov,
                          float* __restrict__ context) {
    int b = blockIdx.x;
    int t = threadIdx.x;               // 0..1023
    __shared__ float red[32];
    const float* sc = score + (size_t)b * L_;
    const float* mk = mask  + (size_t)b * L_;
    const float* cv = cov   + (size_t)b * L_;

    float s[4];
    float mx = -CUDART_INF_F;
    #pragma unroll
    for (int j = 0; j < 4; j++) {
        s[j] = sc[t + j * 1024];
        mx = fmaxf(mx, s[j]);
    }
    // block max
    mx = warp_max(mx);
    if ((t & 31) == 0) red[t >> 5] = mx;
    __syncthreads();
    if (t < 32) {
        float v = red[t];
        v = warp_max(v);
        red[t] = v;
    }
    __syncthreads();
    mx = red[0];

    float e[4];
    float sum = 0.f;
    #pragma unroll
    for (int j = 0; j < 4; j++) {
        e[j] = __expf(s[j] - mx) * mk[t + j * 1024];
        sum += e[j];
    }
    __syncthreads();
    sum = warp_sum(sum);
    if ((t & 31) == 0) red[t >> 5] = sum;
    __syncthreads();
    if (t < 32) {
        float v = red[t];
        v = warp_sum(v);
        red[t] = v;
    }
    __syncthreads();
    float inv = 1.f / red[0];

    #pragma unroll
    for (int j = 0; j < 4; j++) {
        int idx = t + j * 1024;
        float a = e[j] * inv;
        attn[(size_t)b * L_ + idx]   = a;
        newcov[(size_t)b * L_ + idx] = a + cv[idx];
    }
    // zero context[b, :] (D_ == blockDim)
    context[(size_t)b * D_ + t] = 0.f;
}

// ---------------------------------------------------------------------------
// K4: context[b,d] = sum_l attn[b,l] * enc_output[b,l,d]
// grid (lchunk=32, dchunk=8, b=16); block 128 threads; split-L atomics
// (measured-best config; no __ldcs -- it measured 46.9 vs 46.0 without)
// ---------------------------------------------------------------------------
__global__ void k_context(const float* __restrict__ attn,
                          const float* __restrict__ enc,
                          float* __restrict__ context) {
    int b = blockIdx.z;
    int dchunk = blockIdx.y;
    int lchunk = blockIdx.x;
    int t = threadIdx.x;               // 0..127

    __shared__ float a[128];
    a[t] = attn[(size_t)b * L_ + lchunk * 128 + t];
    __syncthreads();

    const float* base = enc + ((size_t)b * L_ + (size_t)lchunk * 128) * D_
                            + dchunk * 128 + t;
    float acc = 0.f;
    #pragma unroll 8
    for (int l = 0; l < 128; l++) {
        acc = fmaf(a[l], base[(size_t)l * D_], acc);
    }
    atomicAdd(&context[(size_t)b * D_ + dchunk * 128 + t], acc);
}

// ---------------------------------------------------------------------------
extern "C" void kernel_launch(void* const* d_in, const int* in_sizes, int n_in,
                              void* d_out, int out_size) {
    const float* dec_hidden  = (const float*)d_in[0];  // [16,1024]
    const float* enc_output  = (const float*)d_in[1];  // [16,4096,1024]
    const float* enc_feature = (const float*)d_in[2];  // [16,4096,1024]
    const float* enc_mask    = (const float*)d_in[3];  // [16,4096]
    // d_in[4] = sec_attn -- dead code in the reference, unused
    const float* coverage    = (const float*)d_in[5];  // [16,4096]
    const float* W_feat      = (const float*)d_in[6];  // [1024,1024]
    const float* b_feat      = (const float*)d_in[7];  // [1024]
    const float* w_score     = (const float*)d_in[8];  // [1024]
    const float* w_cov       = (const float*)d_in[9];  // [1024]

    float* out = (float*)d_out;
    float* attn_out   = out;                     // [16,4096]
    float* context    = out + B_ * L_;           // [16,1024]
    float* newcov_out = out + B_ * L_ + B_ * D_; // [16,4096]

    float* decf;  cudaGetSymbolAddress((void**)&decf,  g_decfeat);
    float* score; cudaGetSymbolAddress((void**)&score, g_score);

    // K1: dec_feature GEMV — 128x2 blocks, 8 warps each; W streamed once/half
    dim3 g1(D_ / 8, B_ / 8);
    k_decfeat<<<g1, 256>>>(dec_hidden, W_feat, b_feat, decf);

    // K2: scores — 65536 warps, 256 thr/block
    k_score<<<(B_ * L_ * 32) / 256, 256>>>(enc_feature, coverage, w_cov,
                                           w_score, decf, score);

    // K3: softmax + mask + renorm + new_coverage + zero context
    k_softmax<<<B_, 1024>>>(score, enc_mask, coverage,
                            attn_out, newcov_out, context);

    // K4: weighted context accumulation
    dim3 g4(L_ / 128, D_ / 128, B_);
    k_context<<<g4, 128>>>(attn_out, enc_output, context);
}